// round 1
// baseline (speedup 1.0000x reference)
#include <cuda_runtime.h>

// Problem constants (fixed by the reference setup)
#define BZ_ 8
#define NF_ 10000
#define D_  16
#define H_  512
#define W_  512
#define HW_ (H_ * W_)
#define NPIX (BZ_ * HW_)
#define CH_ (D_ + 1)   // 17 output channels

__global__ void __launch_bounds__(256)
render_kernel(const float4* __restrict__ attrs,   // [BZ*NF, 3, 16] as float4[...,12]
              const float*  __restrict__ baryw,   // [BZ, H, W, 3]
              const int*    __restrict__ tri,     // [BZ, H, W]
              float*        __restrict__ out)     // [BZ, 17, H, W]
{
    int p = blockIdx.x * blockDim.x + threadIdx.x;
    if (p >= NPIX) return;

    const int n   = p / HW_;
    const int pix = p - n * HW_;
    float* outp = out + (size_t)n * CH_ * HW_ + pix;

    const int t = tri[p];

    if (t < 0) {
        // background: all channels (incl. vis) are zero
        #pragma unroll
        for (int d = 0; d < CH_; d++)
            outp[(size_t)d * HW_] = 0.0f;
        return;
    }

    const float w0 = baryw[3 * p + 0];
    const float w1 = baryw[3 * p + 1];
    const float w2 = baryw[3 * p + 2];

    // gather 3 vertex attribute rows of 16 floats = 12 float4
    const float4* v = attrs + (size_t)t * 12;

    #pragma unroll
    for (int i = 0; i < 4; i++) {
        const float4 a = v[i];
        const float4 b = v[4 + i];
        const float4 c = v[8 + i];
        float4 r;
        r.x = fmaf(w0, a.x, fmaf(w1, b.x, w2 * c.x));
        r.y = fmaf(w0, a.y, fmaf(w1, b.y, w2 * c.y));
        r.z = fmaf(w0, a.z, fmaf(w1, b.z, w2 * c.z));
        r.w = fmaf(w0, a.w, fmaf(w1, b.w, w2 * c.w));
        outp[(size_t)(4 * i + 0) * HW_] = r.x;
        outp[(size_t)(4 * i + 1) * HW_] = r.y;
        outp[(size_t)(4 * i + 2) * HW_] = r.z;
        outp[(size_t)(4 * i + 3) * HW_] = r.w;
    }
    outp[(size_t)D_ * HW_] = 1.0f;   // visibility channel
}

extern "C" void kernel_launch(void* const* d_in, const int* in_sizes, int n_in,
                              void* d_out, int out_size)
{
    const float4* attrs = (const float4*)d_in[0];
    const float*  baryw = (const float*)d_in[1];
    const int*    tri   = (const int*)d_in[2];
    float*        out   = (float*)d_out;

    const int threads = 256;
    const int blocks  = (NPIX + threads - 1) / threads;
    render_kernel<<<blocks, threads>>>(attrs, baryw, tri, out);
}